// round 5
// baseline (speedup 1.0000x reference)
#include <cuda_runtime.h>

#define Ww 112
#define NP (112*112)
#define NCH 64
#define RS 36                 // shared row stride in float4 units (>= 28+7)
#define SMSZ (61*RS)          // 60 data rows + 1 pad row for edge over-stream

// shared float4-group index of (local row ly, group g).
// additive pair-swizzle: bank-group(ly=a+2l, g) = 4a + a/2 + l + g (mod 8),
// linear in lane l -> conflict-free LDS.128 for lane-stride-2-rows access.
__device__ __forceinline__ int ga(int ly, int g) {
    return ly * RS + ((ly >> 1) & 7) + g;
}

__device__ __forceinline__ float rcpa(float x) {
    float y; asm("rcp.approx.f32 %0, %1;" : "=f"(y) : "f"(x)); return y;
}

__device__ __forceinline__ void unp(float4 q, float* r) {
    r[0]=q.x; r[1]=q.y; r[2]=q.z; r[3]=q.w;
}

// 4 outputs with ONE MUFU.RCP: r = 1/(d0 d1 d2 d3), recover each 1/di.
__device__ __forceinline__ float4 norm4(const float* n, const float* d,
                                        float wgt, float bs) {
    const float d01 = d[0]*d[1], d23 = d[2]*d[3];
    const float r   = rcpa(d01*d23);
    const float r01 = r*d23, r23 = r*d01;
    float4 o;
    o.x = fmaf(wgt*n[0], r01*d[1], bs);
    o.y = fmaf(wgt*n[1], r01*d[0], bs);
    o.z = fmaf(wgt*n[2], r23*d[3], bs);
    o.w = fmaf(wgt*n[3], r23*d[2], bs);
    return o;
}

// 8-wide x 2-tall tile.
// NG: float4 groups loaded per row; TLO: first window col used; NBG: numerator
// group offset rel. gb; MAXS: max window start; O0..O7: per-output starts.
template<int NG,int TLO,int NBG,int MAXS,
         int O0,int O1,int O2,int O3,int O4,int O5,int O6,int O7>
__device__ __forceinline__ void tile(
    const float4* __restrict__ s4,
    int lybase, int gb, int lny, bool two, int mode,
    const float* __restrict__ rk, const float* __restrict__ ck,
    float w25, const float* __restrict__ kerg,
    float sp, float wgt, float bs,
    float4* __restrict__ orow0, float4* __restrict__ orow1)
{
    const int off[8] = {O0,O1,O2,O3,O4,O5,O6,O7};
    float den0[8], den1[8];

    if (mode < 2) {
        // ---- vertical pass (rank-1 rk), streaming 6 rows ----
        float tv0[12], tv1[12];
#pragma unroll
        for (int rr = 0; rr < 6; rr++) {
            const int ly = lybase + rr;
            const float4* p = s4 + ga(ly, gb);
            float rv[16];
            unp(p[0], rv); unp(p[1], rv+4); unp(p[2], rv+8);
            if (NG == 4) unp(p[3], rv+12);
            if (rr == 0) {
                const float w = rk[0];
#pragma unroll
                for (int k = 0; k < 12; k++) tv0[k] = w * rv[TLO+k];
            } else if (rr < 5) {
                const float w = rk[rr];
#pragma unroll
                for (int k = 0; k < 12; k++) tv0[k] = fmaf(w, rv[TLO+k], tv0[k]);
            }
            if (rr == 1) {
                const float w = rk[0];
#pragma unroll
                for (int k = 0; k < 12; k++) tv1[k] = w * rv[TLO+k];
            } else if (rr >= 2) {
                const float w = rk[rr-1];
#pragma unroll
                for (int k = 0; k < 12; k++) tv1[k] = fmaf(w, rv[TLO+k], tv1[k]);
            }
        }
        if (!two) {
#pragma unroll
            for (int k = 0; k < 12; k++) tv1[k] = tv0[k];
        }
        if (mode == 0) {
            // uniform-ck fast path: sliding 5-sums
            float h0[MAXS+1], h1[MAXS+1];
            h0[0] = ((tv0[0]+tv0[1]) + (tv0[2]+tv0[3])) + tv0[4];
            h1[0] = ((tv1[0]+tv1[1]) + (tv1[2]+tv1[3])) + tv1[4];
#pragma unroll
            for (int s = 1; s <= MAXS; s++) {
                h0[s] = h0[s-1] - tv0[s-1] + tv0[s+4];
                h1[s] = h1[s-1] - tv1[s-1] + tv1[s+4];
            }
#pragma unroll
            for (int j = 0; j < 8; j++) {
                den0[j] = fmaf(w25, h0[off[j]], sp);
                den1[j] = fmaf(w25, h1[off[j]], sp);
            }
        } else {
#pragma unroll
            for (int j = 0; j < 8; j++) {
                float a0 = 0.0f, a1 = 0.0f;
#pragma unroll
                for (int t = 0; t < 5; t++) {
                    a0 = fmaf(ck[t], tv0[off[j]+t], a0);
                    a1 = fmaf(ck[t], tv1[off[j]+t], a1);
                }
                den0[j] = sp + a0; den1[j] = sp + a1;
            }
        }
    } else {
        // ---- general 25-tap fallback ----
        float a0[8], a1[8];
#pragma unroll
        for (int j = 0; j < 8; j++) { a0[j] = 0.0f; a1[j] = 0.0f; }
#pragma unroll
        for (int rr = 0; rr < 6; rr++) {
            const int ly = lybase + rr;
            const float4* p = s4 + ga(ly, gb);
            float rv[16];
            unp(p[0], rv); unp(p[1], rv+4); unp(p[2], rv+8);
            if (NG == 4) unp(p[3], rv+12);
            if (rr < 5) {
#pragma unroll
                for (int t = 0; t < 5; t++) {
                    const float w = __ldg(kerg + rr*5 + t);
#pragma unroll
                    for (int j = 0; j < 8; j++)
                        a0[j] = fmaf(w, rv[TLO+off[j]+t], a0[j]);
                }
            }
            if (rr >= 1) {
#pragma unroll
                for (int t = 0; t < 5; t++) {
                    const float w = __ldg(kerg + (rr-1)*5 + t);
#pragma unroll
                    for (int j = 0; j < 8; j++)
                        a1[j] = fmaf(w, rv[TLO+off[j]+t], a1[j]);
                }
            }
        }
        if (!two) {
#pragma unroll
            for (int j = 0; j < 8; j++) a1[j] = a0[j];
        }
#pragma unroll
        for (int j = 0; j < 8; j++) { den0[j] = sp + a0[j]; den1[j] = sp + a1[j]; }
    }

    // ---- numerators (rows lny, lny+1 share the pair-swizzle) + stores ----
    float n0[8], n1[8];
    {
        const float4* np0 = s4 + ga(lny,     gb);
        const float4* np1 = s4 + ga(lny + 1, gb);
        unp(np0[NBG], n0); unp(np0[NBG+1], n0+4);
        unp(np1[NBG], n1); unp(np1[NBG+1], n1+4);
    }
    orow0[0] = norm4(n0,     den0,     wgt, bs);
    orow0[1] = norm4(n0 + 4, den0 + 4, wgt, bs);
    orow1[0] = norm4(n1,     den1,     wgt, bs);
    orow1[1] = norm4(n1 + 4, den1 + 4, wgt, bs);
}

__global__ __launch_bounds__(256, 5)
void bionorm_kernel(const float* __restrict__ x,
                    const float* __restrict__ sigma,
                    const float* __restrict__ pow_p,
                    const float* __restrict__ ker,
                    const float* __restrict__ weight,
                    const float* __restrict__ bias,
                    float* __restrict__ out)
{
    __shared__ float4 s4[SMSZ];   // 35136 B

    const int bid   = blockIdx.x;
    const int plane = bid >> 1;
    const int half  = bid & 1;
    const int c     = plane & (NCH - 1);
    const int r0    = half ? 52 : 0;
    const int nrows = half ? 60 : 58;
    const int yo0   = half * 56;

    const float* __restrict__ xin = x + (size_t)plane * NP;
    float* __restrict__ po        = out + (size_t)plane * NP;

    const float p  = pow_p[c];
    const bool  p2 = (p == 2.0f);

    // ---- Phase 1: float4 load + x^p -> shared (pad row 60 never written) ----
    const float4* __restrict__ xin4 =
        reinterpret_cast<const float4*>(xin + r0 * Ww);
    const int ntot = nrows * 28;
    for (int i = threadIdx.x; i < ntot; i += 256) {
        const int ly = i / 28;
        const int g  = i - ly * 28;
        float4 v = xin4[i];
        float4 rq;
        if (p2) {
            rq.x = v.x*v.x; rq.y = v.y*v.y; rq.z = v.z*v.z; rq.w = v.w*v.w;
        } else {
            rq.x = __powf(v.x, p); rq.y = __powf(v.y, p);
            rq.z = __powf(v.z, p); rq.w = __powf(v.w, p);
        }
        s4[ga(ly, g)] = rq;
    }

    // ---- per-channel params: rank-1 + uniform detection (block-uniform) ----
    const float* __restrict__ kerg = ker + c * 25;
    float maxa = 0.0f, best = -1.0f; int pi = 0;
#pragma unroll
    for (int i = 0; i < 25; i++) {
        const float a = fabsf(__ldg(kerg + i));
        maxa = fmaxf(maxa, a);
        if (a > best) { best = a; pi = i; }
    }
    const int i0 = pi / 5, j0 = pi - i0 * 5;

    float rk[5], ck[5];
    int mode = 2;
    if (maxa > 0.0f) {
        const float inv = 1.0f / __ldg(kerg + pi);
#pragma unroll
        for (int i = 0; i < 5; i++) rk[i] = __ldg(kerg + i*5 + j0) * inv;
#pragma unroll
        for (int j = 0; j < 5; j++) ck[j] = __ldg(kerg + i0*5 + j);
        bool sep = true;
        const float tol = 1e-6f * maxa;
#pragma unroll
        for (int i = 0; i < 5; i++)
#pragma unroll
            for (int j = 0; j < 5; j++)
                if (fabsf(fmaf(-rk[i], ck[j], __ldg(kerg + i*5 + j))) > tol)
                    sep = false;
        if (sep) {
            bool uni = true;
            const float utol = 1e-6f * fabsf(ck[0]);
#pragma unroll
            for (int j = 1; j < 5; j++)
                if (fabsf(ck[j] - ck[0]) > utol) uni = false;
            mode = uni ? 0 : 1;
        }
    } else {
#pragma unroll
        for (int i = 0; i < 5; i++) { rk[i] = 0.0f; ck[i] = 0.0f; }
        mode = 0;   // zero kernel: uniform with w25 = 0
    }
    const float w25 = ck[0];

    const float sgm = sigma[c];
    const float sp  = p2 ? sgm*sgm : __powf(sgm, p);
    const float wgt = weight[c];
    const float bs  = bias[c];

    __syncthreads();

    // ---- Phase 2: 8-wide x 2-tall tiles; lanes take consecutive row-pairs ----
    for (int idx = threadIdx.x; idx < 14 * 28; idx += 256) {
        const int xg = idx / 28;
        const int yp = idx - xg * 28;
        const int y0 = (yp << 1) + yo0;
        const int c0 = min(max(y0,     2), 109);
        const int c1 = min(max(y0 + 1, 2), 109);
        const bool two = (c1 != c0);
        const int lybase = c0 - 2 - r0;     // stream rows lybase..lybase+5
        const int lny    = y0 - r0;

        float4* orow0 = reinterpret_cast<float4*>(po + y0      * Ww + (xg << 3));
        float4* orow1 = reinterpret_cast<float4*>(po + (y0+1)  * Ww + (xg << 3));

        if (xg == 0)
            tile<3,0,0,5, 0,0,0,1,2,3,4,5>(s4, lybase, 0,        lny, two, mode,
                rk, ck, w25, kerg, sp, wgt, bs, orow0, orow1);
        else if (xg == 13)
            tile<3,2,1,5, 0,1,2,3,4,5,5,5>(s4, lybase, 25,       lny, two, mode,
                rk, ck, w25, kerg, sp, wgt, bs, orow0, orow1);
        else
            tile<4,2,1,7, 0,1,2,3,4,5,6,7>(s4, lybase, 2*xg - 1, lny, two, mode,
                rk, ck, w25, kerg, sp, wgt, bs, orow0, orow1);
    }
}

extern "C" void kernel_launch(void* const* d_in, const int* in_sizes, int n_in,
                              void* d_out, int out_size)
{
    const float* x      = (const float*)d_in[0];
    const float* sigma  = (const float*)d_in[1];
    const float* pow_p  = (const float*)d_in[2];
    const float* ker    = (const float*)d_in[3];
    const float* weight = (const float*)d_in[4];
    const float* bias   = (const float*)d_in[5];
    float* out = (float*)d_out;

    bionorm_kernel<<<32 * NCH * 2, 256>>>(x, sigma, pow_p, ker,
                                          weight, bias, out);
}

// round 6
// speedup vs baseline: 1.7058x; 1.7058x over previous
#include <cuda_runtime.h>

#define Ww 112
#define NP (112*112)
#define NCH 64
#define RS 33                 // shared row stride in float4 units (odd mod 8)
#define SMSZ (60*RS)          // 31680 B

__device__ __forceinline__ float rcpa(float x) {
    float y; asm("rcp.approx.f32 %0, %1;" : "=f"(y) : "f"(x)); return y;
}

__device__ __forceinline__ void unp(float4 q, float* r) {
    r[0]=q.x; r[1]=q.y; r[2]=q.z; r[3]=q.w;
}

// 4 outputs with ONE MUFU.RCP: r = 1/(d0 d1 d2 d3), recover each 1/di.
__device__ __forceinline__ float4 norm4(const float* n, const float* d,
                                        float wgt, float bs) {
    const float d01 = d[0]*d[1], d23 = d[2]*d[3];
    const float r   = rcpa(d01*d23);
    const float r01 = r*d23, r23 = r*d01;
    float4 o;
    o.x = fmaf(wgt*n[0], r01*d[1], bs);
    o.y = fmaf(wgt*n[1], r01*d[0], bs);
    o.z = fmaf(wgt*n[2], r23*d[3], bs);
    o.w = fmaf(wgt*n[3], r23*d[2], bs);
    return o;
}

// 8-wide x 1-row tile. NG: float4 groups per row; TLO: first window col used;
// NBG: numerator group offset rel. gb; MAXS: max window start; TW: valid tv
// entries; O0..O7: per-output window starts.
template<int NG,int TLO,int NBG,int MAXS,int TW,
         int O0,int O1,int O2,int O3,int O4,int O5,int O6,int O7>
__device__ __forceinline__ void tile(
    const float4* __restrict__ s4,
    int lybase, int gb, int lny, int mode,
    const float* __restrict__ rk, const float* __restrict__ ck,
    float w25, const float* __restrict__ kerg,
    float sp, float wgt, float bs,
    float4* __restrict__ orow)
{
    const int off[8] = {O0,O1,O2,O3,O4,O5,O6,O7};
    float den[8];

    if (mode < 2) {
        // ---- vertical pass (rank-1 rk) over 5 rows ----
        float tv[TW];
#pragma unroll
        for (int rr = 0; rr < 5; rr++) {
            const float4* p = s4 + (lybase + rr) * RS + gb;
            float rv[16];
            unp(p[0], rv); unp(p[1], rv+4); unp(p[2], rv+8);
            if (NG == 4) unp(p[3], rv+12);
            const float w = rk[rr];
            if (rr == 0) {
#pragma unroll
                for (int k = 0; k < TW; k++) tv[k] = w * rv[TLO+k];
            } else {
#pragma unroll
                for (int k = 0; k < TW; k++) tv[k] = fmaf(w, rv[TLO+k], tv[k]);
            }
        }
        if (mode == 0) {
            // uniform-ck: sliding 5-sums
            float h[MAXS+1];
            h[0] = ((tv[0]+tv[1]) + (tv[2]+tv[3])) + tv[4];
#pragma unroll
            for (int s = 1; s <= MAXS; s++)
                h[s] = h[s-1] - tv[s-1] + tv[s+4];
#pragma unroll
            for (int j = 0; j < 8; j++)
                den[j] = fmaf(w25, h[off[j]], sp);
        } else {
#pragma unroll
            for (int j = 0; j < 8; j++) {
                float a = 0.0f;
#pragma unroll
                for (int t = 0; t < 5; t++)
                    a = fmaf(ck[t], tv[off[j]+t], a);
                den[j] = sp + a;
            }
        }
    } else {
        // ---- general 25-tap fallback ----
        float a[8];
#pragma unroll
        for (int j = 0; j < 8; j++) a[j] = 0.0f;
#pragma unroll
        for (int rr = 0; rr < 5; rr++) {
            const float4* p = s4 + (lybase + rr) * RS + gb;
            float rv[16];
            unp(p[0], rv); unp(p[1], rv+4); unp(p[2], rv+8);
            if (NG == 4) unp(p[3], rv+12);
#pragma unroll
            for (int t = 0; t < 5; t++) {
                const float w = __ldg(kerg + rr*5 + t);
#pragma unroll
                for (int j = 0; j < 8; j++)
                    a[j] = fmaf(w, rv[TLO+off[j]+t], a[j]);
            }
        }
#pragma unroll
        for (int j = 0; j < 8; j++) den[j] = sp + a[j];
    }

    // ---- numerator + normalize + vectorized stores ----
    float n[8];
    {
        const float4* np = s4 + lny * RS + gb + NBG;
        unp(np[0], n); unp(np[1], n+4);
    }
    orow[0] = norm4(n,     den,     wgt, bs);
    orow[1] = norm4(n + 4, den + 4, wgt, bs);
}

__global__ __launch_bounds__(256, 5)
void bionorm_kernel(const float* __restrict__ x,
                    const float* __restrict__ sigma,
                    const float* __restrict__ pow_p,
                    const float* __restrict__ ker,
                    const float* __restrict__ weight,
                    const float* __restrict__ bias,
                    float* __restrict__ out)
{
    __shared__ float4 s4[SMSZ];

    const int bid   = blockIdx.x;
    const int plane = bid >> 1;
    const int half  = bid & 1;
    const int c     = plane & (NCH - 1);
    const int r0    = half ? 52 : 0;
    const int nrows = half ? 60 : 58;
    const int yo0   = half * 56;

    const float* __restrict__ xin = x + (size_t)plane * NP;
    float* __restrict__ po        = out + (size_t)plane * NP;

    const float p  = pow_p[c];
    const bool  p2 = (p == 2.0f);

    // ---- Phase 1: float4 load + x^p -> shared ----
    const float4* __restrict__ xin4 =
        reinterpret_cast<const float4*>(xin + r0 * Ww);
    const int ntot = nrows * 28;
    for (int i = threadIdx.x; i < ntot; i += 256) {
        const int ly = i / 28;
        const int g  = i - ly * 28;
        float4 v = xin4[i];
        float4 rq;
        if (p2) {
            rq.x = v.x*v.x; rq.y = v.y*v.y; rq.z = v.z*v.z; rq.w = v.w*v.w;
        } else {
            rq.x = __powf(v.x, p); rq.y = __powf(v.y, p);
            rq.z = __powf(v.z, p); rq.w = __powf(v.w, p);
        }
        s4[ly * RS + g] = rq;
    }

    // ---- per-channel params: rank-1 + uniform detection (block-uniform) ----
    const float* __restrict__ kerg = ker + c * 25;
    float maxa = 0.0f, best = -1.0f; int pi = 0;
#pragma unroll
    for (int i = 0; i < 25; i++) {
        const float a = fabsf(__ldg(kerg + i));
        maxa = fmaxf(maxa, a);
        if (a > best) { best = a; pi = i; }
    }
    const int i0 = pi / 5, j0 = pi - i0 * 5;

    float rk[5], ck[5];
    int mode = 2;
    if (maxa > 0.0f) {
        const float inv = 1.0f / __ldg(kerg + pi);
#pragma unroll
        for (int i = 0; i < 5; i++) rk[i] = __ldg(kerg + i*5 + j0) * inv;
#pragma unroll
        for (int j = 0; j < 5; j++) ck[j] = __ldg(kerg + i0*5 + j);
        bool sep = true;
        const float tol = 1e-6f * maxa;
#pragma unroll
        for (int i = 0; i < 5; i++)
#pragma unroll
            for (int j = 0; j < 5; j++)
                if (fabsf(fmaf(-rk[i], ck[j], __ldg(kerg + i*5 + j))) > tol)
                    sep = false;
        if (sep) {
            bool uni = true;
            const float utol = 1e-6f * fabsf(ck[0]);
#pragma unroll
            for (int j = 1; j < 5; j++)
                if (fabsf(ck[j] - ck[0]) > utol) uni = false;
            mode = uni ? 0 : 1;
        }
    } else {
#pragma unroll
        for (int i = 0; i < 5; i++) { rk[i] = 0.0f; ck[i] = 0.0f; }
        mode = 0;   // zero kernel: uniform with w25 = 0
    }
    const float w25 = ck[0];

    const float sgm = sigma[c];
    const float sp  = p2 ? sgm*sgm : __powf(sgm, p);
    const float wgt = weight[c];
    const float bs  = bias[c];

    __syncthreads();

    // ---- Phase 2: 8-wide x 1-row tiles; lanes take consecutive rows ----
    // RS=33 is odd mod 8 -> lane y-stride 1 gives conflict-free LDS.128
    for (int idx = threadIdx.x; idx < 14 * 56; idx += 256) {
        const int xg = idx / 56;
        const int y  = idx - xg * 56 + yo0;
        const int cy = min(max(y, 2), 109);
        const int lybase = cy - 2 - r0;
        const int lny    = y - r0;

        float4* orow = reinterpret_cast<float4*>(po + y * Ww + (xg << 3));

        if (xg == 0)
            tile<3,0,0,5,10, 0,0,0,1,2,3,4,5>(s4, lybase, 0,        lny, mode,
                rk, ck, w25, kerg, sp, wgt, bs, orow);
        else if (xg == 13)
            tile<3,2,1,5,10, 0,1,2,3,4,5,5,5>(s4, lybase, 25,       lny, mode,
                rk, ck, w25, kerg, sp, wgt, bs, orow);
        else
            tile<4,2,1,7,12, 0,1,2,3,4,5,6,7>(s4, lybase, 2*xg - 1, lny, mode,
                rk, ck, w25, kerg, sp, wgt, bs, orow);
    }
}

extern "C" void kernel_launch(void* const* d_in, const int* in_sizes, int n_in,
                              void* d_out, int out_size)
{
    const float* x      = (const float*)d_in[0];
    const float* sigma  = (const float*)d_in[1];
    const float* pow_p  = (const float*)d_in[2];
    const float* ker    = (const float*)d_in[3];
    const float* weight = (const float*)d_in[4];
    const float* bias   = (const float*)d_in[5];
    float* out = (float*)d_out;

    bionorm_kernel<<<32 * NCH * 2, 256>>>(x, sigma, pow_p, ker,
                                          weight, bias, out);
}